// round 3
// baseline (speedup 1.0000x reference)
#include <cuda_runtime.h>
#include <cuda_bf16.h>

// PositionalEncoding: out[pos,2i]=sin(pos*w_i), out[pos,2i+1]=cos(pos*w_i),
// w_i = 10000^{-i/512}, d_model=1024, seq_len = out_size/1024. X unused.
//
// R2 post-mortem: latency-bound (issue=33%, occ=40.5%, nothing saturated).
// Fixes: (1) ROWS_PER_BLOCK 16->8 => grid 1024 => ~86% occupancy;
// (2) cheap seeds: powf -> exp2f (MUFU.EX2), step-angle sincos (<=1 rad)
// -> __sincosf; only the 2 large start angles use accurate sincosf;
// (3) no per-row bounds check on the common divisible path.
// Target: L2 store floor ~3us for 33.5MB.

#define D_MODEL 1024
#define D_HALF  (D_MODEL / 2)          // 512 pairs per row
#define THREADS 256                    // each thread: 2 adjacent pairs -> float4
#define ROWS_PER_BLOCK 8

// log2(10000) / 512
#define NEG_K2  (-0.02595256324130752f)

__global__ __launch_bounds__(THREADS, 8)
void pe_kernel(float4* __restrict__ out, int seq_len) {
    const int t  = threadIdx.x;        // 0..255
    const int i0 = 2 * t;              // pair columns owned by this thread
    const int i1 = 2 * t + 1;

    // inverse frequencies via EX2: w = 2^(-i * log2(1e4)/512)
    const float w0 = exp2f((float)i0 * NEG_K2);
    const float w1 = exp2f((float)i1 * NEG_K2);

    const int row0 = blockIdx.x * ROWS_PER_BLOCK;
    if (row0 >= seq_len) return;

    // Start angles (up to ~8191 rad): accurate sincosf. Two independent
    // calls -> ILP-2 through the polynomial chains.
    float s0, c0, s1, c1;
    sincosf((float)row0 * w0, &s0, &c0);
    sincosf((float)row0 * w1, &s1, &c1);

    // Step angles are w <= 1 rad: fast hardware path is plenty accurate.
    float sw0, cw0, sw1, cw1;
    __sincosf(w0, &sw0, &cw0);
    __sincosf(w1, &sw1, &cw1);

    float4* p = out + (size_t)row0 * (D_MODEL / 4) + t;

    if (row0 + ROWS_PER_BLOCK <= seq_len) {
        #pragma unroll
        for (int r = 0; r < ROWS_PER_BLOCK; r++) {
            *p = make_float4(s0, c0, s1, c1);
            p += (D_MODEL / 4);
            float ns0 = fmaf(s0, cw0,  c0 * sw0);
            float nc0 = fmaf(c0, cw0, -s0 * sw0);
            float ns1 = fmaf(s1, cw1,  c1 * sw1);
            float nc1 = fmaf(c1, cw1, -s1 * sw1);
            s0 = ns0; c0 = nc0; s1 = ns1; c1 = nc1;
        }
    } else {
        const int rows = seq_len - row0;
        for (int r = 0; r < rows; r++) {
            *p = make_float4(s0, c0, s1, c1);
            p += (D_MODEL / 4);
            float ns0 = fmaf(s0, cw0,  c0 * sw0);
            float nc0 = fmaf(c0, cw0, -s0 * sw0);
            float ns1 = fmaf(s1, cw1,  c1 * sw1);
            float nc1 = fmaf(c1, cw1, -s1 * sw1);
            s0 = ns0; c0 = nc0; s1 = ns1; c1 = nc1;
        }
    }
}

extern "C" void kernel_launch(void* const* d_in, const int* in_sizes, int n_in,
                              void* d_out, int out_size) {
    (void)d_in; (void)in_sizes; (void)n_in;
    const int seq_len = out_size / D_MODEL;    // 8192
    float4* out = (float4*)d_out;

    const int grid = (seq_len + ROWS_PER_BLOCK - 1) / ROWS_PER_BLOCK;  // 1024
    pe_kernel<<<grid, THREADS>>>(out, seq_len);
}

// round 4
// speedup vs baseline: 1.0059x; 1.0059x over previous
#include <cuda_runtime.h>
#include <cuda_bf16.h>

// PositionalEncoding: out[pos,2i]=sin(pos*w_i), out[pos,2i+1]=cos(pos*w_i),
// w_i = 10000^{-i/512}, d_model=1024, seq_len = out_size/1024. X unused.
//
// R3: kill the accurate-sincosf seed (was the dominant serial chain).
// Seed = fp32 angle (same as the JAX reference computes) + 3-instr
// Cody-Waite reduction mod 2pi + __sincosf (MUFU) on the reduced arg.
//   C1 = 6.28125 (exact in 9 bits -> fmaf(-n,C1,theta) exact),
//   C2 = 2pi - C1; n <= 1304 -> reduction error ~2e-7 rad.
// Then 8 rows of angle-addition rotation (4 FMA/row) + STG.128.
// Target: L2 store floor ~3us for 33.5MB.

#define D_MODEL 1024
#define D_HALF  (D_MODEL / 2)
#define THREADS 256                    // each thread: 2 adjacent pairs -> float4
#define ROWS_PER_BLOCK 8

#define NEG_K2   (-0.02595256324130752f)   // -log2(10000)/512
#define INV_2PI  (0.15915494309189535f)
#define TWO_PI_HI (6.28125f)               // exact in 9 mantissa bits
#define TWO_PI_LO (0.0019353071795864769f) // 2pi - TWO_PI_HI

__device__ __forceinline__ void sincos_big(float theta, float* s, float* c) {
    // theta in [0, ~8200): reduce mod 2pi with 2-term Cody-Waite, then MUFU.
    float n = rintf(theta * INV_2PI);
    float r = fmaf(-n, TWO_PI_HI, theta);
    r = fmaf(-n, TWO_PI_LO, r);
    __sincosf(r, s, c);
}

__global__ __launch_bounds__(THREADS, 8)
void pe_kernel(float4* __restrict__ out, int seq_len) {
    const int t  = threadIdx.x;        // 0..255
    const int i0 = 2 * t;
    const int i1 = 2 * t + 1;

    // inverse frequencies via EX2
    const float w0 = exp2f((float)i0 * NEG_K2);
    const float w1 = exp2f((float)i1 * NEG_K2);

    const int row0 = blockIdx.x * ROWS_PER_BLOCK;
    if (row0 >= seq_len) return;

    // Seeds: fp32 angle product (matches reference) + cheap reduction.
    float s0, c0, s1, c1;
    sincos_big((float)row0 * w0, &s0, &c0);
    sincos_big((float)row0 * w1, &s1, &c1);

    // Step rotations: w <= 1 rad, MUFU directly.
    float sw0, cw0, sw1, cw1;
    __sincosf(w0, &sw0, &cw0);
    __sincosf(w1, &sw1, &cw1);

    float4* p = out + (size_t)row0 * (D_MODEL / 4) + t;

    if (row0 + ROWS_PER_BLOCK <= seq_len) {
        #pragma unroll
        for (int r = 0; r < ROWS_PER_BLOCK; r++) {
            *p = make_float4(s0, c0, s1, c1);
            p += (D_MODEL / 4);
            float ns0 = fmaf(s0, cw0,  c0 * sw0);
            float nc0 = fmaf(c0, cw0, -s0 * sw0);
            float ns1 = fmaf(s1, cw1,  c1 * sw1);
            float nc1 = fmaf(c1, cw1, -s1 * sw1);
            s0 = ns0; c0 = nc0; s1 = ns1; c1 = nc1;
        }
    } else {
        const int rows = seq_len - row0;
        for (int r = 0; r < rows; r++) {
            *p = make_float4(s0, c0, s1, c1);
            p += (D_MODEL / 4);
            float ns0 = fmaf(s0, cw0,  c0 * sw0);
            float nc0 = fmaf(c0, cw0, -s0 * sw0);
            float ns1 = fmaf(s1, cw1,  c1 * sw1);
            float nc1 = fmaf(c1, cw1, -s1 * sw1);
            s0 = ns0; c0 = nc0; s1 = ns1; c1 = nc1;
        }
    }
}

extern "C" void kernel_launch(void* const* d_in, const int* in_sizes, int n_in,
                              void* d_out, int out_size) {
    (void)d_in; (void)in_sizes; (void)n_in;
    const int seq_len = out_size / D_MODEL;    // 8192
    float4* out = (float4*)d_out;

    const int grid = (seq_len + ROWS_PER_BLOCK - 1) / ROWS_PER_BLOCK;  // 1024
    pe_kernel<<<grid, THREADS>>>(out, seq_len);
}

// round 6
// speedup vs baseline: 1.2206x; 1.2135x over previous
#include <cuda_runtime.h>
#include <cuda_bf16.h>

// PositionalEncoding: out[pos,2i]=sin(pos*w_i), out[pos,2i+1]=cos(pos*w_i),
// w_i = 10000^{-i/512}, d_model=1024, seq_len = out_size/1024. X unused.
//
// R5: R4's dual-chain kernel with the accuracy bug fixed. R4 failed (7e-3)
// because w1 = w0 * DELTA_W used a constant wrong by 9e-6 rel -> 0.07 rad
// phase error at pos=8191. Fix: w1 via its own exp2f (exact same path that
// passed at 6.9e-5 in R3). Structure kept: two independent rotation chains
// (even/odd rows) stepping by double angle 2w -> half serial FMA depth,
// 2x STG.128 in flight per loop iteration.

#define D_MODEL 1024
#define THREADS 256                    // each thread: 2 adjacent pairs -> float4
#define ROWS_PER_BLOCK 8
#define ROW_F4  (D_MODEL / 4)          // 256 float4 per row

#define NEG_K2    (-0.02595256324130752f)   // -log2(10000)/512
#define INV_2PI   (0.15915494309189535f)
#define TWO_PI_HI (6.28125f)                // exact in 9 mantissa bits
#define TWO_PI_LO (0.0019353071795864769f)  // 2pi - TWO_PI_HI

__device__ __forceinline__ void sincos_big(float theta, float* s, float* c) {
    // theta in [0, ~8200): 2-term Cody-Waite reduction mod 2pi, then MUFU.
    float n = rintf(theta * INV_2PI);
    float r = fmaf(-n, TWO_PI_HI, theta);
    r = fmaf(-n, TWO_PI_LO, r);
    __sincosf(r, s, c);
}

__global__ __launch_bounds__(THREADS, 8)
void pe_kernel(float4* __restrict__ out, int seq_len) {
    const int t = threadIdx.x;             // 0..255; owns pair cols 2t, 2t+1

    // BOTH inverse frequencies via exp2f (accuracy-critical).
    const float w0 = exp2f((float)(2 * t)     * NEG_K2);
    const float w1 = exp2f((float)(2 * t + 1) * NEG_K2);

    const int row0 = blockIdx.x * ROWS_PER_BLOCK;
    if (row0 >= seq_len) return;

    // Chain A seed: even rows (angles via fp32 product, same as reference).
    float sA0, cA0, sA1, cA1;
    sincos_big((float)row0 * w0, &sA0, &cA0);
    sincos_big((float)row0 * w1, &sA1, &cA1);

    // 1-row step (w <= 1 rad): MUFU path.
    float sw0, cw0, sw1, cw1;
    __sincosf(w0, &sw0, &cw0);
    __sincosf(w1, &sw1, &cw1);

    // Chain B seed = chain A rotated by one row.
    float sB0 = fmaf(sA0, cw0,  cA0 * sw0);
    float cB0 = fmaf(cA0, cw0, -sA0 * sw0);
    float sB1 = fmaf(sA1, cw1,  cA1 * sw1);
    float cB1 = fmaf(cA1, cw1, -sA1 * sw1);

    // 2-row step via double-angle: sin2w = 2 sw cw, cos2w = 1 - 2 sw^2.
    const float s20 = 2.0f * sw0 * cw0;
    const float c20 = fmaf(-2.0f * sw0, sw0, 1.0f);
    const float s21 = 2.0f * sw1 * cw1;
    const float c21 = fmaf(-2.0f * sw1, sw1, 1.0f);

    float4* p = out + (size_t)row0 * ROW_F4 + t;

    if (row0 + ROWS_PER_BLOCK <= seq_len) {
        #pragma unroll
        for (int r = 0; r < ROWS_PER_BLOCK / 2; r++) {
            p[0]      = make_float4(sA0, cA0, sA1, cA1);   // even row
            p[ROW_F4] = make_float4(sB0, cB0, sB1, cB1);   // odd row
            p += 2 * ROW_F4;
            // Rotate both chains by 2 rows — fully independent FMA trees.
            float nsA0 = fmaf(sA0, c20,  cA0 * s20);
            float ncA0 = fmaf(cA0, c20, -sA0 * s20);
            float nsA1 = fmaf(sA1, c21,  cA1 * s21);
            float ncA1 = fmaf(cA1, c21, -sA1 * s21);
            float nsB0 = fmaf(sB0, c20,  cB0 * s20);
            float ncB0 = fmaf(cB0, c20, -sB0 * s20);
            float nsB1 = fmaf(sB1, c21,  cB1 * s21);
            float ncB1 = fmaf(cB1, c21, -sB1 * s21);
            sA0 = nsA0; cA0 = ncA0; sA1 = nsA1; cA1 = ncA1;
            sB0 = nsB0; cB0 = ncB0; sB1 = nsB1; cB1 = ncB1;
        }
    } else {
        // Generic tail (seq_len not divisible by ROWS_PER_BLOCK).
        const int rows = seq_len - row0;
        for (int r = 0; r < rows; r += 2) {
            p[0] = make_float4(sA0, cA0, sA1, cA1);
            if (r + 1 < rows) p[ROW_F4] = make_float4(sB0, cB0, sB1, cB1);
            p += 2 * ROW_F4;
            float nsA0 = fmaf(sA0, c20,  cA0 * s20);
            float ncA0 = fmaf(cA0, c20, -sA0 * s20);
            float nsA1 = fmaf(sA1, c21,  cA1 * s21);
            float ncA1 = fmaf(cA1, c21, -sA1 * s21);
            float nsB0 = fmaf(sB0, c20,  cB0 * s20);
            float ncB0 = fmaf(cB0, c20, -sB0 * s20);
            float nsB1 = fmaf(sB1, c21,  cB1 * s21);
            float ncB1 = fmaf(cB1, c21, -sB1 * s21);
            sA0 = nsA0; cA0 = ncA0; sA1 = nsA1; cA1 = ncA1;
            sB0 = nsB0; cB0 = ncB0; sB1 = nsB1; cB1 = ncB1;
        }
    }
}

extern "C" void kernel_launch(void* const* d_in, const int* in_sizes, int n_in,
                              void* d_out, int out_size) {
    (void)d_in; (void)in_sizes; (void)n_in;
    const int seq_len = out_size / D_MODEL;    // 8192
    float4* out = (float4*)d_out;

    const int grid = (seq_len + ROWS_PER_BLOCK - 1) / ROWS_PER_BLOCK;  // 1024
    pe_kernel<<<grid, THREADS>>>(out, seq_len);
}

// round 7
// speedup vs baseline: 1.2657x; 1.0369x over previous
#include <cuda_runtime.h>
#include <cuda_bf16.h>

// PositionalEncoding: out[pos,2i]=sin(pos*w_i), out[pos,2i+1]=cos(pos*w_i),
// w_i = 10000^{-i/512}, d_model=1024, seq_len = out_size/1024. X unused.
//
// R6: kernel dur flat (~8us) across R2-R6 despite big per-warp changes;
// all pipes idle. Model: chip-level floor = CTA ramp (T_ovh~2.6us) + L2
// store drain (~2.8us), poorly overlapped at grid=1024/one wave.
// Test: ROWS_PER_BLOCK 4, grid 2048 (two waves) — wave-2 launch overlaps
// wave-1 store drain. Dual rotation chains kept (serial depth now 2).

#define D_MODEL 1024
#define THREADS 256                    // each thread: 2 adjacent pairs -> float4
#define ROWS_PER_BLOCK 4
#define ROW_F4  (D_MODEL / 4)          // 256 float4 per row

#define NEG_K2    (-0.02595256324130752f)   // -log2(10000)/512
#define INV_2PI   (0.15915494309189535f)
#define TWO_PI_HI (6.28125f)                // exact in 9 mantissa bits
#define TWO_PI_LO (0.0019353071795864769f)  // 2pi - TWO_PI_HI

__device__ __forceinline__ void sincos_big(float theta, float* s, float* c) {
    // theta in [0, ~8200): 2-term Cody-Waite reduction mod 2pi, then MUFU.
    float n = rintf(theta * INV_2PI);
    float r = fmaf(-n, TWO_PI_HI, theta);
    r = fmaf(-n, TWO_PI_LO, r);
    __sincosf(r, s, c);
}

__global__ __launch_bounds__(THREADS, 8)
void pe_kernel(float4* __restrict__ out, int seq_len) {
    const int t = threadIdx.x;             // 0..255; owns pair cols 2t, 2t+1

    // Inverse frequencies (accuracy-critical: each via its own exp2f).
    const float w0 = exp2f((float)(2 * t)     * NEG_K2);
    const float w1 = exp2f((float)(2 * t + 1) * NEG_K2);

    const int row0 = blockIdx.x * ROWS_PER_BLOCK;
    if (row0 >= seq_len) return;

    // Chain A seed: even rows (fp32 angle product, same as reference).
    float sA0, cA0, sA1, cA1;
    sincos_big((float)row0 * w0, &sA0, &cA0);
    sincos_big((float)row0 * w1, &sA1, &cA1);

    // 1-row step (w <= 1 rad): MUFU path.
    float sw0, cw0, sw1, cw1;
    __sincosf(w0, &sw0, &cw0);
    __sincosf(w1, &sw1, &cw1);

    // Chain B seed = chain A rotated by one row.
    float sB0 = fmaf(sA0, cw0,  cA0 * sw0);
    float cB0 = fmaf(cA0, cw0, -sA0 * sw0);
    float sB1 = fmaf(sA1, cw1,  cA1 * sw1);
    float cB1 = fmaf(cA1, cw1, -sA1 * sw1);

    // 2-row step via double-angle: sin2w = 2 sw cw, cos2w = 1 - 2 sw^2.
    const float s20 = 2.0f * sw0 * cw0;
    const float c20 = fmaf(-2.0f * sw0, sw0, 1.0f);
    const float s21 = 2.0f * sw1 * cw1;
    const float c21 = fmaf(-2.0f * sw1, sw1, 1.0f);

    float4* p = out + (size_t)row0 * ROW_F4 + t;

    if (row0 + ROWS_PER_BLOCK <= seq_len) {
        #pragma unroll
        for (int r = 0; r < ROWS_PER_BLOCK / 2; r++) {
            p[0]      = make_float4(sA0, cA0, sA1, cA1);   // even row
            p[ROW_F4] = make_float4(sB0, cB0, sB1, cB1);   // odd row
            p += 2 * ROW_F4;
            float nsA0 = fmaf(sA0, c20,  cA0 * s20);
            float ncA0 = fmaf(cA0, c20, -sA0 * s20);
            float nsA1 = fmaf(sA1, c21,  cA1 * s21);
            float ncA1 = fmaf(cA1, c21, -sA1 * s21);
            float nsB0 = fmaf(sB0, c20,  cB0 * s20);
            float ncB0 = fmaf(cB0, c20, -sB0 * s20);
            float nsB1 = fmaf(sB1, c21,  cB1 * s21);
            float ncB1 = fmaf(cB1, c21, -sB1 * s21);
            sA0 = nsA0; cA0 = ncA0; sA1 = nsA1; cA1 = ncA1;
            sB0 = nsB0; cB0 = ncB0; sB1 = nsB1; cB1 = ncB1;
        }
    } else {
        const int rows = seq_len - row0;
        for (int r = 0; r < rows; r += 2) {
            p[0] = make_float4(sA0, cA0, sA1, cA1);
            if (r + 1 < rows) p[ROW_F4] = make_float4(sB0, cB0, sB1, cB1);
            p += 2 * ROW_F4;
            float nsA0 = fmaf(sA0, c20,  cA0 * s20);
            float ncA0 = fmaf(cA0, c20, -sA0 * s20);
            float nsA1 = fmaf(sA1, c21,  cA1 * s21);
            float ncA1 = fmaf(cA1, c21, -sA1 * s21);
            float nsB0 = fmaf(sB0, c20,  cB0 * s20);
            float ncB0 = fmaf(cB0, c20, -sB0 * s20);
            float nsB1 = fmaf(sB1, c21,  cB1 * s21);
            float ncB1 = fmaf(cB1, c21, -sB1 * s21);
            sA0 = nsA0; cA0 = ncA0; sA1 = nsA1; cA1 = ncA1;
            sB0 = nsB0; cB0 = ncB0; sB1 = nsB1; cB1 = ncB1;
        }
    }
}

extern "C" void kernel_launch(void* const* d_in, const int* in_sizes, int n_in,
                              void* d_out, int out_size) {
    (void)d_in; (void)in_sizes; (void)n_in;
    const int seq_len = out_size / D_MODEL;    // 8192
    float4* out = (float4*)d_out;

    const int grid = (seq_len + ROWS_PER_BLOCK - 1) / ROWS_PER_BLOCK;  // 2048
    pe_kernel<<<grid, THREADS>>>(out, seq_len);
}